// round 15
// baseline (speedup 1.0000x reference)
#include <cuda_runtime.h>
#include <cstdint>

// Problem constants (BSZ=1)
#define DROPE  64
#define VQK    48   // 192/4 float4 per output row
#define VKV    64   // 256/4 float4 per kv row

// Each block: 256 threads, 1024 contiguous elements of ONE region.
// A/C/E use 256-bit (float4-pair) accesses: 2 pairs per thread.
// B/D use 4x float4 per thread; rope partner via warp shuffle (lane^8).
#define BLK_A   8192u   // q_nope copy:  8388608 el
#define BLK_B   4096u   // q rope:       4194304 el
#define BLK_C  16384u   // kv copy:     16777216 el
#define BLK_D   4096u   // k_pe rope:    4194304 el
#define BLK_E   4096u   // zero fill:    4194304 el
#define NBLOCKS (BLK_A + BLK_B + BLK_C + BLK_D + BLK_E)   // 36864

__device__ __forceinline__ void ldg256(const float4* p, float4& a, float4& b)
{
    asm volatile("ld.global.nc.v8.f32 {%0,%1,%2,%3,%4,%5,%6,%7}, [%8];"
        : "=f"(a.x), "=f"(a.y), "=f"(a.z), "=f"(a.w),
          "=f"(b.x), "=f"(b.y), "=f"(b.z), "=f"(b.w)
        : "l"(p));
}

__device__ __forceinline__ void stg256cs(float4* p, float4 a, float4 b)
{
    asm volatile("st.global.cs.v8.f32 [%0], {%1,%2,%3,%4,%5,%6,%7,%8};"
        :: "l"(p),
           "f"(a.x), "f"(a.y), "f"(a.z), "f"(a.w),
           "f"(b.x), "f"(b.y), "f"(b.z), "f"(b.w)
        : "memory");
}

// Rope partner from the lane holding the other half (lane ^ 8 within the
// 16-lane row segment); avoids a duplicate L1 load of the same lines.
__device__ __forceinline__ float4 shfl_partner(float4 x)
{
    float4 r;
    r.x = __shfl_xor_sync(0xffffffffu, x.x, 8);
    r.y = __shfl_xor_sync(0xffffffffu, x.y, 8);
    r.z = __shfl_xor_sync(0xffffffffu, x.z, 8);
    r.w = __shfl_xor_sync(0xffffffffu, x.w, 8);
    return r;
}

__device__ __forceinline__ float4 rope4(float4 x, float4 xp, float4 cc, float4 ss, float sgn)
{
    float4 r;
    r.x = fmaf(sgn * xp.x, ss.x, x.x * cc.x);
    r.y = fmaf(sgn * xp.y, ss.y, x.y * cc.y);
    r.z = fmaf(sgn * xp.z, ss.z, x.z * cc.z);
    r.w = fmaf(sgn * xp.w, ss.w, x.w * cc.w);
    return r;
}

__global__ void __launch_bounds__(256)
fused_mla_rope_kernel(const float4* __restrict__ q,
                      const float4* __restrict__ kv,
                      const float4* __restrict__ k_pe,
                      const float*  __restrict__ cos_t,
                      const float*  __restrict__ sin_t,
                      const int*    __restrict__ pos,
                      float4* __restrict__ out_q,
                      float4* __restrict__ out_kv)
{
    const unsigned b   = blockIdx.x;
    const unsigned tid = threadIdx.x;

    if (b < BLK_A) {
        // ---- A: q_nope copy via 256-bit pairs (2 pairs = 4 float4 / thread) ----
        unsigned j0 = b * 512u + tid;             // pair index
        unsigned idx[2];
        float4 va[2], vb[2];
        #pragma unroll
        for (int u = 0; u < 2; u++) {
            unsigned j = j0 + u * 256u;
            unsigned row = j >> 4;                // 16 pairs per 32-v4 segment
            unsigned c = (j & 15u) * 2u;          // even
            idx[u] = row * VQK + c;
        }
        #pragma unroll
        for (int u = 0; u < 2; u++) ldg256(&q[idx[u]], va[u], vb[u]);
        #pragma unroll
        for (int u = 0; u < 2; u++) stg256cs(&out_q[idx[u]], va[u], vb[u]);
    } else if (b < BLK_A + BLK_B) {
        // ---- B: q rope (4x float4 ILP, partner via shfl) ----
        // Block start is 1024-aligned so c = tid & 15 for every u.
        unsigned base_i = (b - BLK_A) * 1024u + tid;
        unsigned c = tid & 15u;
        float sgn = (c < 8) ? -1.0f : 1.0f;
        #pragma unroll
        for (int u = 0; u < 4; u++) {
            unsigned i = base_i + u * 256u;
            unsigned row = i >> 4;                // row = s*128 + h
            unsigned s = row >> 7;
            int p = __ldg(&pos[s]);
            unsigned base = row * VQK + 32;

            float4 x  = __ldg(&q[base + c]);
            float4 xp = shfl_partner(x);
            float4 cc = __ldg((const float4*)(cos_t + p * DROPE) + c);
            float4 ss = __ldg((const float4*)(sin_t + p * DROPE) + c);
            __stcs(&out_q[base + c], rope4(x, xp, cc, ss, sgn));
        }
    } else if (b < BLK_A + BLK_B + BLK_C) {
        // ---- C: kv copy via 256-bit pairs ----
        unsigned j0 = (b - (BLK_A + BLK_B)) * 512u + tid;
        unsigned src[2], dst[2];
        float4 va[2], vb[2];
        #pragma unroll
        for (int u = 0; u < 2; u++) {
            unsigned j = j0 + u * 256u;
            unsigned rr = j >> 4;                 // rr = (s*2+slot)*128 + h
            unsigned c = (j & 15u) * 2u;          // even
            unsigned h = rr & 127, t = rr >> 7;
            src[u] = (((t >> 1) << 7) + h) * VKV + ((t & 1) << 5) + c;
            dst[u] = rr * VQK + c;
        }
        #pragma unroll
        for (int u = 0; u < 2; u++) ldg256(&kv[src[u]], va[u], vb[u]);
        #pragma unroll
        for (int u = 0; u < 2; u++) stg256cs(&out_kv[dst[u]], va[u], vb[u]);
    } else if (b < BLK_A + BLK_B + BLK_C + BLK_D) {
        // ---- D: rope(k_pe[s]) broadcast -> res_kv slot0 [cols 128:192] ----
        unsigned base_i = (b - (BLK_A + BLK_B + BLK_C)) * 1024u + tid;
        unsigned c = tid & 15u;
        float sgn = (c < 8) ? -1.0f : 1.0f;
        #pragma unroll
        for (int u = 0; u < 4; u++) {
            unsigned i = base_i + u * 256u;
            unsigned row = i >> 4;                // row = s*128 + h
            unsigned s = row >> 7, h = row & 127;
            int p = __ldg(&pos[s]);

            const float4* kp = k_pe + s * (DROPE / 4);
            float4 x  = __ldg(&kp[c]);
            float4 xp = shfl_partner(x);
            float4 cc = __ldg((const float4*)(cos_t + p * DROPE) + c);
            float4 ss = __ldg((const float4*)(sin_t + p * DROPE) + c);

            unsigned dst = ((s << 8) + h) * VQK + 32 + c;   // rw = s*256 + h
            __stcs(&out_kv[dst], rope4(x, xp, cc, ss, sgn));
        }
    } else {
        // ---- E: zero fill via 256-bit pairs -> res_kv slot1 [cols 128:192] ----
        unsigned j0 = (b - (BLK_A + BLK_B + BLK_C + BLK_D)) * 512u + tid;
        const float4 z = make_float4(0.f, 0.f, 0.f, 0.f);
        #pragma unroll
        for (int u = 0; u < 2; u++) {
            unsigned j = j0 + u * 256u;
            unsigned row = j >> 3;                // row = s*128 + h
            unsigned c = (j & 7u) * 2u;           // even, 0..14
            unsigned s = row >> 7, h = row & 127;
            unsigned dst = ((s << 8) + 128 + h) * VQK + 32 + c;
            stg256cs(&out_kv[dst], z, z);
        }
    }
}

extern "C" void kernel_launch(void* const* d_in, const int* in_sizes, int n_in,
                              void* d_out, int out_size)
{
    const float4* q     = (const float4*)d_in[0];
    const float4* kv    = (const float4*)d_in[1];
    const float4* k_pe  = (const float4*)d_in[2];
    const float*  cos_t = (const float*)d_in[3];
    const float*  sin_t = (const float*)d_in[4];
    const int*    pos   = (const int*)d_in[5];

    float4* out_q  = (float4*)d_out;
    float4* out_kv = out_q + (long long)2048 * 128 * VQK;   // + 12,582,912

    fused_mla_rope_kernel<<<NBLOCKS, 256>>>(q, kv, k_pe, cos_t, sin_t, pos,
                                            out_q, out_kv);
}